// round 8
// baseline (speedup 1.0000x reference)
#include <cuda_runtime.h>
#include <cuda_fp16.h>
#include <math.h>
#include <stdint.h>

#define Dm 1024
#define DFF 4096
#define Bb 2048
#define NROW 73728
#define NQ 20480
#define OUTN ((size_t)6*2048*6*1024)

// ---------------- scratch ----------------
__device__ __half g_srch [(size_t)NROW*Dm];
__device__ __half g_kvh  [(size_t)NROW*2048];
__device__ __half g_qsrch[(size_t)NQ*Dm];
__device__ __half g_qh   [(size_t)NQ*Dm];
__device__ __half g_ctxh [(size_t)NQ*Dm];
__device__ __half g_msgh [(size_t)NQ*Dm];
__device__ __half g_a1inh[(size_t)Bb*5120];
__device__ __half g_a2inh[(size_t)Bb*5120];
__device__ float  g_aggv [(size_t)Bb*Dm];
__device__ float  g_nagg [(size_t)Bb*Dm];
__device__ float  g_h1   [(size_t)Bb*5*Dm];
__device__ __half g_h1h  [(size_t)Bb*5*Dm];
__device__ __half g_r1h  [(size_t)Bb*5*DFF];
__device__ float  g_f1   [(size_t)Bb*5*Dm];
__device__ float  g_s1   [(size_t)Bb*Dm];
__device__ __half g_s1h  [(size_t)Bb*Dm];
__device__ __half g_r2h  [(size_t)Bb*DFF];
__device__ float  g_f2   [(size_t)Bb*Dm];
__device__ __half g_wh   [(size_t)31457280];
#define WIN  0
#define WOUT 3145728
#define A1W  4194304
#define A2W  9437184
#define F1W1 14680064
#define F1W2 18874368
#define F2W1 23068672
#define F2W2 27262976

__device__ __forceinline__ uint32_t smem_u32(const void* p) {
    uint32_t a;
    asm("{ .reg .u64 t; cvta.to.shared.u64 t, %1; cvt.u32.u64 %0, t; }" : "=r"(a) : "l"(p));
    return a;
}
__device__ __forceinline__ void cp16(uint32_t dst, const __half* src) {
    asm volatile("cp.async.cg.shared.global [%0], [%1], 16;"
                 :: "r"(dst), "l"(__cvta_generic_to_global(src)) : "memory");
}
#define CP_COMMIT() asm volatile("cp.async.commit_group;" ::: "memory")
#define CP_WAIT(n)  asm volatile("cp.async.wait_group %0;" :: "n"(n) : "memory")

// ---------------- f16 mma.sync GEMM: C[M,N]=A[M,K]@W[N,K]^T+bias ----------------
// CTA tile 128x256, BK=32, 512 thr (16 warps, 4x4), warp tile 32x64.
// 3-stage cp.async pipeline. smem rows padded to 80B -> ldmatrix conflict-free.
// smem: A 3x(128*80) at 0, B 3x(256*80) at 30720. Total 92160 bytes (dynamic).
#define SMB 92160
template<int EPI, int OUT16>   // EPI: 0 none, 1 relu, 2 sigmoid
__global__ void __launch_bounds__(512, 1) hgemm(
    int M, int N, int K,
    const __half* __restrict__ A, const __half* __restrict__ W,
    const float* __restrict__ bias, void* __restrict__ Cv)
{
    extern __shared__ char dsm[];
    const uint32_t base = smem_u32(dsm);
    const int tid = threadIdx.x;
    const int warp = tid >> 5, lane = tid & 31;
    const int wm = warp & 3, wn = warp >> 2;
    const long bm = (long)blockIdx.y * 128;
    const long bn = (long)blockIdx.x * 256;
    const int gr = lane >> 2, tg = lane & 3;

    float acc[2][8][4];
    #pragma unroll
    for (int i = 0; i < 2; i++)
        #pragma unroll
        for (int j = 0; j < 8; j++) {
            acc[i][j][0] = 0.f; acc[i][j][1] = 0.f;
            acc[i][j][2] = 0.f; acc[i][j][3] = 0.f;
        }

    const int S = K >> 5;
    auto stage = [&](int s, int b) {
        const int k0 = s << 5;
        {
            int r = tid >> 2, c = tid & 3;   // A: 512 chunks, 1/thread
            cp16(base + (uint32_t)(b*10240 + r*80 + c*16),
                 A + (bm + r)*(long)K + k0 + c*8);
        }
        #pragma unroll
        for (int i = 0; i < 2; i++) {        // B: 1024 chunks, 2/thread
            int ch = tid + (i << 9);
            int r = ch >> 2, c = ch & 3;
            cp16(base + 30720u + (uint32_t)(b*20480 + r*80 + c*16),
                 W + (bn + r)*(long)K + k0 + c*8);
        }
    };

    stage(0, 0); CP_COMMIT();
    stage(1, 1); CP_COMMIT();

    for (int s = 0; s < S; s++) {
        if (s + 1 < S) { CP_WAIT(1); } else { CP_WAIT(0); }
        __syncthreads();
        if (s + 2 < S) { stage(s + 2, (s + 2) % 3); CP_COMMIT(); }
        const uint32_t ab = base + (uint32_t)((s % 3) * 10240);
        const uint32_t bb = base + 30720u + (uint32_t)((s % 3) * 20480);

        #pragma unroll
        for (int ks = 0; ks < 2; ks++) {
            uint32_t af[2][4], bf[8][2];
            #pragma unroll
            for (int mt = 0; mt < 2; mt++) {
                int row = wm*32 + mt*16 + (lane & 15);
                uint32_t p = ab + (uint32_t)(row*80 + (ks*2 + (lane >> 4))*16);
                asm volatile("ldmatrix.sync.aligned.m8n8.x4.shared.b16 {%0,%1,%2,%3}, [%4];"
                    : "=r"(af[mt][0]), "=r"(af[mt][1]), "=r"(af[mt][2]), "=r"(af[mt][3])
                    : "r"(p));
            }
            #pragma unroll
            for (int np = 0; np < 4; np++) {
                int q = lane >> 3;
                int nrow = wn*64 + np*16 + (q >> 1)*8 + (lane & 7);
                uint32_t p = bb + (uint32_t)(nrow*80 + (ks*2 + (q & 1))*16);
                asm volatile("ldmatrix.sync.aligned.m8n8.x4.shared.b16 {%0,%1,%2,%3}, [%4];"
                    : "=r"(bf[2*np][0]), "=r"(bf[2*np][1]),
                      "=r"(bf[2*np+1][0]), "=r"(bf[2*np+1][1])
                    : "r"(p));
            }
            #pragma unroll
            for (int mt = 0; mt < 2; mt++)
                #pragma unroll
                for (int nt = 0; nt < 8; nt++) {
                    asm volatile(
                        "mma.sync.aligned.m16n8k16.row.col.f32.f16.f16.f32 "
                        "{%0,%1,%2,%3}, {%4,%5,%6,%7}, {%8,%9}, {%0,%1,%2,%3};"
                        : "+f"(acc[mt][nt][0]), "+f"(acc[mt][nt][1]),
                          "+f"(acc[mt][nt][2]), "+f"(acc[mt][nt][3])
                        : "r"(af[mt][0]), "r"(af[mt][1]), "r"(af[mt][2]), "r"(af[mt][3]),
                          "r"(bf[nt][0]), "r"(bf[nt][1]));
                }
        }
    }

    // epilogue
    #pragma unroll
    for (int mt = 0; mt < 2; mt++) {
        long row0 = bm + wm*32 + mt*16 + gr;
        #pragma unroll
        for (int nt = 0; nt < 8; nt++) {
            int col0 = (int)bn + wn*64 + nt*8 + tg*2;
            float bv0 = __ldg(bias + col0);
            float bv1 = __ldg(bias + col0 + 1);
            float v00 = acc[mt][nt][0] + bv0;
            float v01 = acc[mt][nt][1] + bv1;
            float v10 = acc[mt][nt][2] + bv0;
            float v11 = acc[mt][nt][3] + bv1;
            if (EPI == 1) {
                v00 = fmaxf(v00, 0.f); v01 = fmaxf(v01, 0.f);
                v10 = fmaxf(v10, 0.f); v11 = fmaxf(v11, 0.f);
            }
            if (EPI == 2) {
                v00 = 1.f/(1.f+__expf(-v00)); v01 = 1.f/(1.f+__expf(-v01));
                v10 = 1.f/(1.f+__expf(-v10)); v11 = 1.f/(1.f+__expf(-v11));
            }
            if (OUT16) {
                __half* C = (__half*)Cv;
                *(__half2*)(C + row0*(long)N + col0)     = __floats2half2_rn(v00, v01);
                *(__half2*)(C + (row0+8)*(long)N + col0) = __floats2half2_rn(v10, v11);
            } else {
                float* C = (float*)Cv;
                *(float2*)(C + row0*(long)N + col0)     = make_float2(v00, v01);
                *(float2*)(C + (row0+8)*(long)N + col0) = make_float2(v10, v11);
            }
        }
    }
}

// ---------------- small kernels ----------------
__global__ void k_cvt(const float4* __restrict__ s, uint2* __restrict__ d, long n4) {
    long i = (long)blockIdx.x * blockDim.x + threadIdx.x;
    if (i >= n4) return;
    float4 v = s[i];
    __half2 a = __floats2half2_rn(v.x, v.y), b = __floats2half2_rn(v.z, v.w);
    d[i] = make_uint2(*(uint32_t*)&a, *(uint32_t*)&b);
}
__global__ void k_src(const float* __restrict__ F, const float* __restrict__ R,
                      __half* __restrict__ srch) {
    long i8 = (long)blockIdx.x * blockDim.x + threadIdx.x;
    long r = i8 >> 7; int d8 = (int)(i8 & 127);
    int l = (int)(r % 6); long sbq = r / 6;
    const float4* F4 = (const float4*)F;
    float4 v0 = F4[i8*2], v1 = F4[i8*2+1];
    if (l > 0) {
        const float4* R4 = (const float4*)R;
        long rb = (sbq*5 + (l-1))*256 + d8*2;
        float4 e0 = R4[rb], e1 = R4[rb+1];
        v0.x+=e0.x; v0.y+=e0.y; v0.z+=e0.z; v0.w+=e0.w;
        v1.x+=e1.x; v1.y+=e1.y; v1.z+=e1.z; v1.w+=e1.w;
    }
    __half2 h0=__floats2half2_rn(v0.x,v0.y), h1=__floats2half2_rn(v0.z,v0.w);
    __half2 h2=__floats2half2_rn(v1.x,v1.y), h3=__floats2half2_rn(v1.z,v1.w);
    ((uint4*)srch)[i8] = make_uint4(*(uint32_t*)&h0,*(uint32_t*)&h1,*(uint32_t*)&h2,*(uint32_t*)&h3);
}
__global__ void k_gatherq(const __half* __restrict__ s, __half* __restrict__ q) {
    long idx = (long)blockIdx.x * blockDim.x + threadIdx.x;
    int i = (int)(idx >> 7), d8 = (int)(idx & 127);
    long rs;
    if (i < 10240) { int sp = i/2048, b = i%2048; rs = ((long)(sp+1)*2048 + b)*6; }
    else           { int j = i-10240; int m = j/2048, b = j%2048; rs = (long)b*6 + m + 1; }
    ((uint4*)q)[idx] = ((const uint4*)s)[rs*128 + d8];
}
__global__ void k_attn(const __half* __restrict__ q, const __half* __restrict__ kv,
                       __half* __restrict__ ctx) {
    int i = blockIdx.x, seq;
    if (i < 10240) { int sp = i/2048, b = i%2048; seq = (sp+1)*2048 + b; }
    else           { seq = (i - 10240) % 2048; }
    const int warp = threadIdx.x >> 5, lane = threadIdx.x & 31;
    const __half* kb = kv + (long)seq * 12288;
    for (int h = warp; h < 16; h += 8) {
        float2 qf = __half22float2(*(const __half2*)(q + (long)i*1024 + h*64 + lane*2));
        float sc[6];
        #pragma unroll
        for (int j = 0; j < 6; j++) {
            float2 kf = __half22float2(*(const __half2*)(kb + j*2048 + h*64 + lane*2));
            float p = qf.x*kf.x + qf.y*kf.y;
            #pragma unroll
            for (int o = 16; o; o >>= 1) p += __shfl_xor_sync(0xffffffffu, p, o);
            sc[j] = p * 0.125f;
        }
        float mx = sc[0];
        #pragma unroll
        for (int j = 1; j < 6; j++) mx = fmaxf(mx, sc[j]);
        float sum = 0.f;
        #pragma unroll
        for (int j = 0; j < 6; j++) { sc[j] = __expf(sc[j]-mx); sum += sc[j]; }
        float inv = 1.f/sum, o0 = 0.f, o1 = 0.f;
        #pragma unroll
        for (int j = 0; j < 6; j++) {
            float2 vf = __half22float2(*(const __half2*)(kb + j*2048 + 1024 + h*64 + lane*2));
            o0 = fmaf(sc[j]*inv, vf.x, o0); o1 = fmaf(sc[j]*inv, vf.y, o1);
        }
        *(__half2*)(ctx + (long)i*1024 + h*64 + lane*2) = __floats2half2_rn(o0, o1);
    }
}
__global__ void k_scatter(const __half* __restrict__ msg,
                          __half* __restrict__ a1, __half* __restrict__ a2) {
    long idx = (long)blockIdx.x * blockDim.x + threadIdx.x;
    int i = (int)(idx >> 7), d8 = (int)(idx & 127);
    uint4 v = ((const uint4*)msg)[idx];
    if (i < 10240) { int sp = i/2048, b = i%2048; ((uint4*)a1)[(long)b*640 + sp*128 + d8] = v; }
    else { int j = i-10240; int m = j/2048, b = j%2048; ((uint4*)a2)[(long)b*640 + m*128 + d8] = v; }
}
__device__ __forceinline__ float bsum(float v) {
    __shared__ float sh[9];
    int lane = threadIdx.x & 31, w = threadIdx.x >> 5;
    #pragma unroll
    for (int o = 16; o; o >>= 1) v += __shfl_xor_sync(0xffffffffu, v, o);
    if (lane == 0) sh[w] = v;
    __syncthreads();
    if (w == 0) {
        float r = (lane < 8) ? sh[lane] : 0.f;
        #pragma unroll
        for (int o = 4; o; o >>= 1) r += __shfl_xor_sync(0xffffffffu, r, o);
        if (lane == 0) sh[8] = r;
    }
    __syncthreads();
    float out = sh[8];
    __syncthreads();
    return out;
}
__device__ __forceinline__ void ln_row(const float* pa, const float* pb,
                                       const float* g, const float* bv,
                                       float* po, __half* ph) {
    int tid = threadIdx.x;
    float v[4];
    #pragma unroll
    for (int t = 0; t < 4; t++) v[t] = pa[tid + t*256] + pb[tid + t*256];
    float mu = bsum(v[0]+v[1]+v[2]+v[3]) * (1.f/1024.f);
    float qv = 0.f;
    #pragma unroll
    for (int t = 0; t < 4; t++) { float d = v[t]-mu; qv += d*d; }
    float r = rsqrtf(bsum(qv) * (1.f/1024.f) + 1e-5f);
    #pragma unroll
    for (int t = 0; t < 4; t++) {
        int idx = tid + t*256;
        float o = (v[t]-mu)*r*g[idx] + bv[idx];
        po[idx] = o;
        if (ph) ph[idx] = __float2half_rn(o);
    }
}
__global__ void k_ln1(const float* F, const float* aggv, const float* g, const float* bv,
                      float* out, __half* outh) {
    int row = blockIdx.x; int b = row/5, m = row%5;
    ln_row(F + ((long)b*6+1+m)*1024, aggv + (long)b*1024, g, bv,
           out + (long)row*1024, outh + (long)row*1024);
}
__global__ void k_ln2(const float* h1, const float* f1, const float* g, const float* bv,
                      float* out) {
    int row = blockIdx.x; int b = row/5, m = row%5;
    ln_row(h1 + (long)row*1024, f1 + (long)row*1024, g, bv,
           out + ((long)b*6+1+m)*1024, (__half*)0);
}
__global__ void k_ln3(const float* F, const float* nagg, const float* g, const float* bv,
                      float* out, __half* outh) {
    int b = blockIdx.x;
    ln_row(F + (long)b*6144, nagg + (long)b*1024, g, bv,
           out + (long)b*1024, outh + (long)b*1024);
}
__global__ void k_ln4(const float* s1, const float* f2, const float* g, const float* bv,
                      float* out) {
    int b = blockIdx.x;
    ln_row(s1 + (long)b*1024, f2 + (long)b*1024, g, bv, out + (long)b*6144, (__half*)0);
}

// ---------------- host ----------------
template<typename T> static T* sym(const void* s) {
    void* p = nullptr; cudaGetSymbolAddress(&p, s); return (T*)p;
}
static void cvt(const float* s, __half* d, long n) {
    long n4 = n/4;
    k_cvt<<<(unsigned)((n4+255)/256), 256>>>((const float4*)s, (uint2*)d, n4);
}

extern "C" void kernel_launch(void* const* d_in, const int* in_sizes, int n_in,
                              void* d_out, int out_size) {
    (void)in_sizes; (void)n_in; (void)out_size;
    const float *F=(const float*)d_in[0], *R=(const float*)d_in[1];
    const float *w_in=(const float*)d_in[2], *b_in=(const float*)d_in[3];
    const float *w_out=(const float*)d_in[4], *b_out=(const float*)d_in[5];
    const float *ln1g=(const float*)d_in[6], *ln1b=(const float*)d_in[7];
    const float *ln2g=(const float*)d_in[8], *ln2b=(const float*)d_in[9];
    const float *ln3g=(const float*)d_in[10], *ln3b=(const float*)d_in[11];
    const float *ln4g=(const float*)d_in[12], *ln4b=(const float*)d_in[13];
    const float *f1w1=(const float*)d_in[14], *f1b1=(const float*)d_in[15];
    const float *f1w2=(const float*)d_in[16], *f1b2=(const float*)d_in[17];
    const float *f2w1=(const float*)d_in[18], *f2b1=(const float*)d_in[19];
    const float *f2w2=(const float*)d_in[20], *f2b2=(const float*)d_in[21];
    const float *a1w=(const float*)d_in[22], *a1b=(const float*)d_in[23];
    const float *a2w=(const float*)d_in[24], *a2b=(const float*)d_in[25];
    float* out = (float*)d_out;

    __half *srch=sym<__half>(g_srch), *kvh=sym<__half>(g_kvh);
    __half *qsrch=sym<__half>(g_qsrch), *qh=sym<__half>(g_qh);
    __half *ctxh=sym<__half>(g_ctxh), *msgh=sym<__half>(g_msgh);
    __half *a1inh=sym<__half>(g_a1inh), *a2inh=sym<__half>(g_a2inh);
    float *aggv=sym<float>(g_aggv), *nagg=sym<float>(g_nagg);
    float *h1=sym<float>(g_h1), *f1=sym<float>(g_f1);
    float *s1=sym<float>(g_s1), *f2=sym<float>(g_f2);
    __half *h1h=sym<__half>(g_h1h), *r1h=sym<__half>(g_r1h);
    __half *s1h=sym<__half>(g_s1h), *r2h=sym<__half>(g_r2h);
    __half *wh=sym<__half>(g_wh);

    cudaFuncSetAttribute(hgemm<0,1>, cudaFuncAttributeMaxDynamicSharedMemorySize, SMB);
    cudaFuncSetAttribute(hgemm<0,0>, cudaFuncAttributeMaxDynamicSharedMemorySize, SMB);
    cudaFuncSetAttribute(hgemm<1,1>, cudaFuncAttributeMaxDynamicSharedMemorySize, SMB);
    cudaFuncSetAttribute(hgemm<2,0>, cudaFuncAttributeMaxDynamicSharedMemorySize, SMB);

    cudaMemcpyAsync(out, F, OUTN*sizeof(float), cudaMemcpyDeviceToDevice, 0);

    cvt(w_in,  wh+WIN,  (long)3072*1024);
    cvt(w_out, wh+WOUT, (long)1024*1024);
    cvt(a1w,   wh+A1W,  (long)1024*5120);
    cvt(a2w,   wh+A2W,  (long)1024*5120);
    cvt(f1w1,  wh+F1W1, (long)4096*1024);
    cvt(f1w2,  wh+F1W2, (long)1024*4096);
    cvt(f2w1,  wh+F2W1, (long)4096*1024);
    cvt(f2w2,  wh+F2W2, (long)1024*4096);

    k_src<<<NROW/2, 256>>>(F, R, srch);
    k_gatherq<<<NQ/2, 256>>>(srch, qsrch);

    hgemm<0,1><<<dim3(8, NROW/128), 512, SMB>>>(NROW, 2048, 1024,
        srch, wh+WIN+(size_t)1024*1024, b_in+1024, kvh);
    hgemm<0,1><<<dim3(4, NQ/128), 512, SMB>>>(NQ, 1024, 1024, qsrch, wh+WIN, b_in, qh);

    k_attn<<<NQ, 256>>>(qh, kvh, ctxh);

    hgemm<0,1><<<dim3(4, NQ/128), 512, SMB>>>(NQ, 1024, 1024, ctxh, wh+WOUT, b_out, msgh);
    k_scatter<<<NQ/2, 256>>>(msgh, a1inh, a2inh);

    hgemm<2,0><<<dim3(4, Bb/128), 512, SMB>>>(Bb, 1024, 5120, a1inh, wh+A1W, a1b, aggv);
    hgemm<2,0><<<dim3(4, Bb/128), 512, SMB>>>(Bb, 1024, 5120, a2inh, wh+A2W, a2b, nagg);

    k_ln1<<<Bb*5, 256>>>(F, aggv, ln1g, ln1b, h1, h1h);
    hgemm<1,1><<<dim3(16, Bb*5/128), 512, SMB>>>(Bb*5, DFF, 1024, h1h, wh+F1W1, f1b1, r1h);
    hgemm<0,0><<<dim3(4, Bb*5/128), 512, SMB>>>(Bb*5, 1024, DFF, r1h, wh+F1W2, f1b2, f1);
    k_ln2<<<Bb*5, 256>>>(h1, f1, ln2g, ln2b, out);

    k_ln3<<<Bb, 256>>>(F, nagg, ln3g, ln3b, s1, s1h);
    hgemm<1,1><<<dim3(16, Bb/128), 512, SMB>>>(Bb, DFF, 1024, s1h, wh+F2W1, f2b1, r2h);
    hgemm<0,0><<<dim3(4, Bb/128), 512, SMB>>>(Bb, 1024, DFF, r2h, wh+F2W2, f2b2, f2);
    k_ln4<<<Bb, 256>>>(s1, f2, ln4g, ln4b, out);
}

// round 9
// speedup vs baseline: 1.2367x; 1.2367x over previous
#include <cuda_runtime.h>
#include <cuda_fp16.h>
#include <math.h>
#include <stdint.h>

#define Dm 1024
#define DFF 4096
#define Bb 2048
#define NROW 73728
#define NQ 20480
#define OUTN ((size_t)6*2048*6*1024)

// ---------------- scratch ----------------
__device__ __half g_srch [(size_t)NROW*Dm];
__device__ __half g_kvh  [(size_t)NROW*2048];
__device__ __half g_qsrch[(size_t)NQ*Dm];
__device__ __half g_qh   [(size_t)NQ*Dm];
__device__ __half g_ctxh [(size_t)NQ*Dm];
__device__ __half g_msgh [(size_t)NQ*Dm];
__device__ __half g_a1inh[(size_t)Bb*5120];
__device__ __half g_a2inh[(size_t)Bb*5120];
__device__ float  g_aggv [(size_t)Bb*Dm];
__device__ float  g_nagg [(size_t)Bb*Dm];
__device__ float  g_h1   [(size_t)Bb*5*Dm];
__device__ __half g_h1h  [(size_t)Bb*5*Dm];
__device__ __half g_r1h  [(size_t)Bb*5*DFF];
__device__ float  g_f1   [(size_t)Bb*5*Dm];
__device__ float  g_s1   [(size_t)Bb*Dm];
__device__ __half g_s1h  [(size_t)Bb*Dm];
__device__ __half g_r2h  [(size_t)Bb*DFF];
__device__ float  g_f2   [(size_t)Bb*Dm];
__device__ __half g_wh   [(size_t)31457280];
#define WIN  0
#define WOUT 3145728
#define A1W  4194304
#define A2W  9437184
#define F1W1 14680064
#define F1W2 18874368
#define F2W1 23068672
#define F2W2 27262976

__device__ __forceinline__ uint32_t smem_u32(const void* p) {
    uint32_t a;
    asm("{ .reg .u64 t; cvta.to.shared.u64 t, %1; cvt.u32.u64 %0, t; }" : "=r"(a) : "l"(p));
    return a;
}
__device__ __forceinline__ void cp16(uint32_t dst, const __half* src) {
    asm volatile("cp.async.cg.shared.global [%0], [%1], 16;"
                 :: "r"(dst), "l"(__cvta_generic_to_global(src)) : "memory");
}
#define CP_COMMIT() asm volatile("cp.async.commit_group;" ::: "memory")
#define CP_WAIT(n)  asm volatile("cp.async.wait_group %0;" :: "n"(n) : "memory")

// ---------------- f16 mma.sync GEMM: C[M,N]=A[M,K]@W[N,K]^T+bias ----------------
// CTA tile 128x128, BK=32, 256 thr (8 warps 2x4), warp tile 64x32.
// 3-stage cp.async, ONE __syncthreads per K-step. Rows padded to 80B.
// smem/stage: A 10240 + B 10240 = 20480; 3 stages = 61440 B dynamic -> 2 CTA/SM.
#define SMB 61440
template<int EPI, int OUT16>   // EPI: 0 none, 1 relu, 2 sigmoid
__global__ void __launch_bounds__(256, 2) hgemm(
    int M, int N, int K,
    const __half* __restrict__ A, const __half* __restrict__ W,
    const float* __restrict__ bias, void* __restrict__ Cv)
{
    extern __shared__ char dsm[];
    const uint32_t base = smem_u32(dsm);
    const int tid = threadIdx.x;
    const int warp = tid >> 5, lane = tid & 31;
    const int wm = warp >> 2, wn = warp & 3;
    const long bm = (long)blockIdx.y * 128;
    const long bn = (long)blockIdx.x * 128;
    const int gr = lane >> 2, tg = lane & 3;

    float acc[4][4][4];
    #pragma unroll
    for (int i = 0; i < 4; i++)
        #pragma unroll
        for (int j = 0; j < 4; j++) {
            acc[i][j][0] = 0.f; acc[i][j][1] = 0.f;
            acc[i][j][2] = 0.f; acc[i][j][3] = 0.f;
        }

    const int S = K >> 5;
    auto stage = [&](int s, int b) {
        const int k0 = s << 5;
        #pragma unroll
        for (int i = 0; i < 2; i++) {
            int ch = tid + (i << 8);          // 0..511
            int r = ch >> 2, c = ch & 3;
            cp16(base + (uint32_t)(b*20480 + r*80 + c*16),
                 A + (bm + r)*(long)K + k0 + c*8);
            cp16(base + (uint32_t)(b*20480 + 10240 + r*80 + c*16),
                 W + (bn + r)*(long)K + k0 + c*8);
        }
    };

    stage(0, 0); CP_COMMIT();
    stage(1, 1); CP_COMMIT();

    for (int s = 0; s < S; s++) {
        if (s + 1 < S) { CP_WAIT(1); } else { CP_WAIT(0); }
        __syncthreads();
        if (s + 2 < S) { stage(s + 2, (s + 2) % 3); CP_COMMIT(); }
        const uint32_t ab = base + (uint32_t)((s % 3) * 20480);
        const uint32_t bb = ab + 10240u;

        #pragma unroll
        for (int ks = 0; ks < 2; ks++) {
            uint32_t af[4][4], bf[4][2];
            #pragma unroll
            for (int mt = 0; mt < 4; mt++) {
                int row = wm*64 + mt*16 + (lane & 15);
                uint32_t p = ab + (uint32_t)(row*80 + (ks*2 + (lane >> 4))*16);
                asm volatile("ldmatrix.sync.aligned.m8n8.x4.shared.b16 {%0,%1,%2,%3}, [%4];"
                    : "=r"(af[mt][0]), "=r"(af[mt][1]), "=r"(af[mt][2]), "=r"(af[mt][3])
                    : "r"(p));
            }
            #pragma unroll
            for (int np = 0; np < 2; np++) {
                int q = lane >> 3;
                int nrow = wn*32 + np*16 + (q >> 1)*8 + (lane & 7);
                uint32_t p = bb + (uint32_t)(nrow*80 + (ks*2 + (q & 1))*16);
                asm volatile("ldmatrix.sync.aligned.m8n8.x4.shared.b16 {%0,%1,%2,%3}, [%4];"
                    : "=r"(bf[2*np][0]), "=r"(bf[2*np][1]),
                      "=r"(bf[2*np+1][0]), "=r"(bf[2*np+1][1])
                    : "r"(p));
            }
            #pragma unroll
            for (int mt = 0; mt < 4; mt++)
                #pragma unroll
                for (int nt = 0; nt < 4; nt++) {
                    asm volatile(
                        "mma.sync.aligned.m16n8k16.row.col.f32.f16.f16.f32 "
                        "{%0,%1,%2,%3}, {%4,%5,%6,%7}, {%8,%9}, {%0,%1,%2,%3};"
                        : "+f"(acc[mt][nt][0]), "+f"(acc[mt][nt][1]),
                          "+f"(acc[mt][nt][2]), "+f"(acc[mt][nt][3])
                        : "r"(af[mt][0]), "r"(af[mt][1]), "r"(af[mt][2]), "r"(af[mt][3]),
                          "r"(bf[nt][0]), "r"(bf[nt][1]));
                }
        }
    }

    // epilogue
    #pragma unroll
    for (int mt = 0; mt < 4; mt++) {
        long row0 = bm + wm*64 + mt*16 + gr;
        #pragma unroll
        for (int nt = 0; nt < 4; nt++) {
            int col0 = (int)bn + wn*32 + nt*8 + tg*2;
            float bv0 = __ldg(bias + col0);
            float bv1 = __ldg(bias + col0 + 1);
            float v00 = acc[mt][nt][0] + bv0;
            float v01 = acc[mt][nt][1] + bv1;
            float v10 = acc[mt][nt][2] + bv0;
            float v11 = acc[mt][nt][3] + bv1;
            if (EPI == 1) {
                v00 = fmaxf(v00, 0.f); v01 = fmaxf(v01, 0.f);
                v10 = fmaxf(v10, 0.f); v11 = fmaxf(v11, 0.f);
            }
            if (EPI == 2) {
                v00 = 1.f/(1.f+__expf(-v00)); v01 = 1.f/(1.f+__expf(-v01));
                v10 = 1.f/(1.f+__expf(-v10)); v11 = 1.f/(1.f+__expf(-v11));
            }
            if (OUT16) {
                __half* C = (__half*)Cv;
                *(__half2*)(C + row0*(long)N + col0)     = __floats2half2_rn(v00, v01);
                *(__half2*)(C + (row0+8)*(long)N + col0) = __floats2half2_rn(v10, v11);
            } else {
                float* C = (float*)Cv;
                *(float2*)(C + row0*(long)N + col0)     = make_float2(v00, v01);
                *(float2*)(C + (row0+8)*(long)N + col0) = make_float2(v10, v11);
            }
        }
    }
}

// ---------------- small kernels ----------------
__global__ void k_cvt(const float4* __restrict__ s, uint2* __restrict__ d, long n4) {
    long i = (long)blockIdx.x * blockDim.x + threadIdx.x;
    if (i >= n4) return;
    float4 v = s[i];
    __half2 a = __floats2half2_rn(v.x, v.y), b = __floats2half2_rn(v.z, v.w);
    d[i] = make_uint2(*(uint32_t*)&a, *(uint32_t*)&b);
}
__global__ void k_src(const float* __restrict__ F, const float* __restrict__ R,
                      __half* __restrict__ srch) {
    long i8 = (long)blockIdx.x * blockDim.x + threadIdx.x;
    long r = i8 >> 7; int d8 = (int)(i8 & 127);
    int l = (int)(r % 6); long sbq = r / 6;
    const float4* F4 = (const float4*)F;
    float4 v0 = F4[i8*2], v1 = F4[i8*2+1];
    if (l > 0) {
        const float4* R4 = (const float4*)R;
        long rb = (sbq*5 + (l-1))*256 + d8*2;
        float4 e0 = R4[rb], e1 = R4[rb+1];
        v0.x+=e0.x; v0.y+=e0.y; v0.z+=e0.z; v0.w+=e0.w;
        v1.x+=e1.x; v1.y+=e1.y; v1.z+=e1.z; v1.w+=e1.w;
    }
    __half2 h0=__floats2half2_rn(v0.x,v0.y), h1=__floats2half2_rn(v0.z,v0.w);
    __half2 h2=__floats2half2_rn(v1.x,v1.y), h3=__floats2half2_rn(v1.z,v1.w);
    ((uint4*)srch)[i8] = make_uint4(*(uint32_t*)&h0,*(uint32_t*)&h1,*(uint32_t*)&h2,*(uint32_t*)&h3);
}
__global__ void k_gatherq(const __half* __restrict__ s, __half* __restrict__ q) {
    long idx = (long)blockIdx.x * blockDim.x + threadIdx.x;
    int i = (int)(idx >> 7), d8 = (int)(idx & 127);
    long rs;
    if (i < 10240) { int sp = i/2048, b = i%2048; rs = ((long)(sp+1)*2048 + b)*6; }
    else           { int j = i-10240; int m = j/2048, b = j%2048; rs = (long)b*6 + m + 1; }
    ((uint4*)q)[idx] = ((const uint4*)s)[rs*128 + d8];
}
__global__ void k_attn(const __half* __restrict__ q, const __half* __restrict__ kv,
                       __half* __restrict__ ctx) {
    int i = blockIdx.x, seq;
    if (i < 10240) { int sp = i/2048, b = i%2048; seq = (sp+1)*2048 + b; }
    else           { seq = (i - 10240) % 2048; }
    const int warp = threadIdx.x >> 5, lane = threadIdx.x & 31;
    const __half* kb = kv + (long)seq * 12288;
    for (int h = warp; h < 16; h += 8) {
        float2 qf = __half22float2(*(const __half2*)(q + (long)i*1024 + h*64 + lane*2));
        float sc[6];
        #pragma unroll
        for (int j = 0; j < 6; j++) {
            float2 kf = __half22float2(*(const __half2*)(kb + j*2048 + h*64 + lane*2));
            float p = qf.x*kf.x + qf.y*kf.y;
            #pragma unroll
            for (int o = 16; o; o >>= 1) p += __shfl_xor_sync(0xffffffffu, p, o);
            sc[j] = p * 0.125f;
        }
        float mx = sc[0];
        #pragma unroll
        for (int j = 1; j < 6; j++) mx = fmaxf(mx, sc[j]);
        float sum = 0.f;
        #pragma unroll
        for (int j = 0; j < 6; j++) { sc[j] = __expf(sc[j]-mx); sum += sc[j]; }
        float inv = 1.f/sum, o0 = 0.f, o1 = 0.f;
        #pragma unroll
        for (int j = 0; j < 6; j++) {
            float2 vf = __half22float2(*(const __half2*)(kb + j*2048 + 1024 + h*64 + lane*2));
            o0 = fmaf(sc[j]*inv, vf.x, o0); o1 = fmaf(sc[j]*inv, vf.y, o1);
        }
        *(__half2*)(ctx + (long)i*1024 + h*64 + lane*2) = __floats2half2_rn(o0, o1);
    }
}
__global__ void k_scatter(const __half* __restrict__ msg,
                          __half* __restrict__ a1, __half* __restrict__ a2) {
    long idx = (long)blockIdx.x * blockDim.x + threadIdx.x;
    int i = (int)(idx >> 7), d8 = (int)(idx & 127);
    uint4 v = ((const uint4*)msg)[idx];
    if (i < 10240) { int sp = i/2048, b = i%2048; ((uint4*)a1)[(long)b*640 + sp*128 + d8] = v; }
    else { int j = i-10240; int m = j/2048, b = j%2048; ((uint4*)a2)[(long)b*640 + m*128 + d8] = v; }
}
__device__ __forceinline__ float bsum(float v) {
    __shared__ float sh[9];
    int lane = threadIdx.x & 31, w = threadIdx.x >> 5;
    #pragma unroll
    for (int o = 16; o; o >>= 1) v += __shfl_xor_sync(0xffffffffu, v, o);
    if (lane == 0) sh[w] = v;
    __syncthreads();
    if (w == 0) {
        float r = (lane < 8) ? sh[lane] : 0.f;
        #pragma unroll
        for (int o = 4; o; o >>= 1) r += __shfl_xor_sync(0xffffffffu, r, o);
        if (lane == 0) sh[8] = r;
    }
    __syncthreads();
    float out = sh[8];
    __syncthreads();
    return out;
}
__device__ __forceinline__ void ln_row(const float* pa, const float* pb,
                                       const float* g, const float* bv,
                                       float* po, __half* ph) {
    int tid = threadIdx.x;
    float v[4];
    #pragma unroll
    for (int t = 0; t < 4; t++) v[t] = pa[tid + t*256] + pb[tid + t*256];
    float mu = bsum(v[0]+v[1]+v[2]+v[3]) * (1.f/1024.f);
    float qv = 0.f;
    #pragma unroll
    for (int t = 0; t < 4; t++) { float d = v[t]-mu; qv += d*d; }
    float r = rsqrtf(bsum(qv) * (1.f/1024.f) + 1e-5f);
    #pragma unroll
    for (int t = 0; t < 4; t++) {
        int idx = tid + t*256;
        float o = (v[t]-mu)*r*g[idx] + bv[idx];
        po[idx] = o;
        if (ph) ph[idx] = __float2half_rn(o);
    }
}
__global__ void k_ln1(const float* F, const float* aggv, const float* g, const float* bv,
                      float* out, __half* outh) {
    int row = blockIdx.x; int b = row/5, m = row%5;
    ln_row(F + ((long)b*6+1+m)*1024, aggv + (long)b*1024, g, bv,
           out + (long)row*1024, outh + (long)row*1024);
}
__global__ void k_ln2(const float* h1, const float* f1, const float* g, const float* bv,
                      float* out) {
    int row = blockIdx.x; int b = row/5, m = row%5;
    ln_row(h1 + (long)row*1024, f1 + (long)row*1024, g, bv,
           out + ((long)b*6+1+m)*1024, (__half*)0);
}
__global__ void k_ln3(const float* F, const float* nagg, const float* g, const float* bv,
                      float* out, __half* outh) {
    int b = blockIdx.x;
    ln_row(F + (long)b*6144, nagg + (long)b*1024, g, bv,
           out + (long)b*1024, outh + (long)b*1024);
}
__global__ void k_ln4(const float* s1, const float* f2, const float* g, const float* bv,
                      float* out) {
    int b = blockIdx.x;
    ln_row(s1 + (long)b*1024, f2 + (long)b*1024, g, bv, out + (long)b*6144, (__half*)0);
}

// ---------------- host ----------------
template<typename T> static T* sym(const void* s) {
    void* p = nullptr; cudaGetSymbolAddress(&p, s); return (T*)p;
}
static void cvt(const float* s, __half* d, long n) {
    long n4 = n/4;
    k_cvt<<<(unsigned)((n4+255)/256), 256>>>((const float4*)s, (uint2*)d, n4);
}

extern "C" void kernel_launch(void* const* d_in, const int* in_sizes, int n_in,
                              void* d_out, int out_size) {
    (void)in_sizes; (void)n_in; (void)out_size;
    const float *F=(const float*)d_in[0], *R=(const float*)d_in[1];
    const float *w_in=(const float*)d_in[2], *b_in=(const float*)d_in[3];
    const float *w_out=(const float*)d_in[4], *b_out=(const float*)d_in[5];
    const float *ln1g=(const float*)d_in[6], *ln1b=(const float*)d_in[7];
    const float *ln2g=(const float*)d_in[8], *ln2b=(const float*)d_in[9];
    const float *ln3g=(const float*)d_in[10], *ln3b=(const float*)d_in[11];
    const float *ln4g=(const float*)d_in[12], *ln4b=(const float*)d_in[13];
    const float *f1w1=(const float*)d_in[14], *f1b1=(const float*)d_in[15];
    const float *f1w2=(const float*)d_in[16], *f1b2=(const float*)d_in[17];
    const float *f2w1=(const float*)d_in[18], *f2b1=(const float*)d_in[19];
    const float *f2w2=(const float*)d_in[20], *f2b2=(const float*)d_in[21];
    const float *a1w=(const float*)d_in[22], *a1b=(const float*)d_in[23];
    const float *a2w=(const float*)d_in[24], *a2b=(const float*)d_in[25];
    float* out = (float*)d_out;

    __half *srch=sym<__half>(g_srch), *kvh=sym<__half>(g_kvh);
    __half *qsrch=sym<__half>(g_qsrch), *qh=sym<__half>(g_qh);
    __half *ctxh=sym<__half>(g_ctxh), *msgh=sym<__half>(g_msgh);
    __half *a1inh=sym<__half>(g_a1inh), *a2inh=sym<__half>(g_a2inh);
    float *aggv=sym<float>(g_aggv), *nagg=sym<float>(g_nagg);
    float *h1=sym<float>(g_h1), *f1=sym<float>(g_f1);
    float *s1=sym<float>(g_s1), *f2=sym<float>(g_f2);
    __half *h1h=sym<__half>(g_h1h), *r1h=sym<__half>(g_r1h);
    __half *s1h=sym<__half>(g_s1h), *r2h=sym<__half>(g_r2h);
    __half *wh=sym<__half>(g_wh);

    cudaFuncSetAttribute(hgemm<0,1>, cudaFuncAttributeMaxDynamicSharedMemorySize, SMB);
    cudaFuncSetAttribute(hgemm<0,0>, cudaFuncAttributeMaxDynamicSharedMemorySize, SMB);
    cudaFuncSetAttribute(hgemm<1,1>, cudaFuncAttributeMaxDynamicSharedMemorySize, SMB);
    cudaFuncSetAttribute(hgemm<2,0>, cudaFuncAttributeMaxDynamicSharedMemorySize, SMB);

    cudaMemcpyAsync(out, F, OUTN*sizeof(float), cudaMemcpyDeviceToDevice, 0);

    cvt(w_in,  wh+WIN,  (long)3072*1024);
    cvt(w_out, wh+WOUT, (long)1024*1024);
    cvt(a1w,   wh+A1W,  (long)1024*5120);
    cvt(a2w,   wh+A2W,  (long)1024*5120);
    cvt(f1w1,  wh+F1W1, (long)4096*1024);
    cvt(f1w2,  wh+F1W2, (long)1024*4096);
    cvt(f2w1,  wh+F2W1, (long)4096*1024);
    cvt(f2w2,  wh+F2W2, (long)1024*4096);

    k_src<<<NROW/2, 256>>>(F, R, srch);
    k_gatherq<<<NQ/2, 256>>>(srch, qsrch);

    hgemm<0,1><<<dim3(16, NROW/128), 256, SMB>>>(NROW, 2048, 1024,
        srch, wh+WIN+(size_t)1024*1024, b_in+1024, kvh);
    hgemm<0,1><<<dim3(8, NQ/128), 256, SMB>>>(NQ, 1024, 1024, qsrch, wh+WIN, b_in, qh);

    k_attn<<<NQ, 256>>>(qh, kvh, ctxh);

    hgemm<0,1><<<dim3(8, NQ/128), 256, SMB>>>(NQ, 1024, 1024, ctxh, wh+WOUT, b_out, msgh);
    k_scatter<<<NQ/2, 256>>>(msgh, a1inh, a2inh);

    hgemm<2,0><<<dim3(8, Bb/128), 256, SMB>>>(Bb, 1024, 5120, a1inh, wh+A1W, a1b, aggv);
    hgemm<2,0><<<dim3(8, Bb/128), 256, SMB>>>(Bb, 1024, 5120, a2inh, wh+A2W, a2b, nagg);

    k_ln1<<<Bb*5, 256>>>(F, aggv, ln1g, ln1b, h1, h1h);
    hgemm<1,1><<<dim3(32, Bb*5/128), 256, SMB>>>(Bb*5, DFF, 1024, h1h, wh+F1W1, f1b1, r1h);
    hgemm<0,0><<<dim3(8, Bb*5/128), 256, SMB>>>(Bb*5, 1024, DFF, r1h, wh+F1W2, f1b2, f1);
    k_ln2<<<Bb*5, 256>>>(h1, f1, ln2g, ln2b, out);

    k_ln3<<<Bb, 256>>>(F, nagg, ln3g, ln3b, s1, s1h);
    hgemm<1,1><<<dim3(32, Bb/128), 256, SMB>>>(Bb, DFF, 1024, s1h, wh+F2W1, f2b1, r2h);
    hgemm<0,0><<<dim3(8, Bb/128), 256, SMB>>>(Bb, 1024, DFF, r2h, wh+F2W2, f2b2, f2);
    k_ln4<<<Bb, 256>>>(s1, f2, ln4g, ln4b, out);
}

// round 10
// speedup vs baseline: 1.4268x; 1.1537x over previous
#include <cuda_runtime.h>
#include <cuda_fp16.h>
#include <math.h>
#include <stdint.h>

#define Dm 1024
#define DFF 4096
#define Bb 2048
#define NROW 73728
#define NQ 20480
#define OUTN ((size_t)6*2048*6*1024)

// ---------------- scratch ----------------
__device__ __half g_srch [(size_t)NROW*Dm];
__device__ __half g_kvh  [(size_t)NROW*2048];
__device__ __half g_qsrch[(size_t)NQ*Dm];
__device__ __half g_qh   [(size_t)NQ*Dm];
__device__ __half g_ctxh [(size_t)NQ*Dm];
__device__ __half g_msgh [(size_t)NQ*Dm];
__device__ __half g_a1inh[(size_t)Bb*5120];
__device__ __half g_a2inh[(size_t)Bb*5120];
__device__ float  g_aggv [(size_t)Bb*Dm];
__device__ float  g_nagg [(size_t)Bb*Dm];
__device__ float  g_h1   [(size_t)Bb*5*Dm];
__device__ __half g_h1h  [(size_t)Bb*5*Dm];
__device__ __half g_r1h  [(size_t)Bb*5*DFF];
__device__ float  g_f1   [(size_t)Bb*5*Dm];
__device__ float  g_s1   [(size_t)Bb*Dm];
__device__ __half g_s1h  [(size_t)Bb*Dm];
__device__ __half g_r2h  [(size_t)Bb*DFF];
__device__ float  g_f2   [(size_t)Bb*Dm];
__device__ __half g_wh   [(size_t)31457280];
// contiguous f16 weight layout (element offsets)
#define WIN  0
#define WOUT 3145728
#define A1W  4194304
#define A2W  9437184
#define F1W1 14680064
#define F1W2 18874368
#define F2W1 23068672
#define F2W2 27262976

__device__ __forceinline__ uint32_t smem_u32(const void* p) {
    uint32_t a;
    asm("{ .reg .u64 t; cvta.to.shared.u64 t, %1; cvt.u32.u64 %0, t; }" : "=r"(a) : "l"(p));
    return a;
}
__device__ __forceinline__ void cp16(uint32_t dst, const __half* src) {
    asm volatile("cp.async.cg.shared.global [%0], [%1], 16;"
                 :: "r"(dst), "l"(__cvta_generic_to_global(src)) : "memory");
}
#define CP_COMMIT() asm volatile("cp.async.commit_group;" ::: "memory")
#define CP_WAIT(n)  asm volatile("cp.async.wait_group %0;" :: "n"(n) : "memory")

// ---------------- f16 mma.sync GEMM, optionally z-batched ----------------
// CTA tile 128x128, BK=64, 256 thr (8 warps 2x4), warp tile 64x32.
// 3-stage cp.async, ONE __syncthreads per K-step. Rows padded to 144B.
// smem/stage: A 18432 + B 18432 = 36864; 3 stages = 110592 B -> 2 CTA/SM.
#define SMB 110592
template<int EPI, int OUT16>   // EPI: 0 none, 1 relu, 2 sigmoid
__global__ void __launch_bounds__(256, 2) hgemm(
    int N, int K,
    int M0, const __half* A0, const __half* W0, const float* b0, void* C0,
    int M1, const __half* A1, const __half* W1, const float* b1, void* C1)
{
    const __half* A; const __half* W; const float* bias; void* Cv; int M;
    if (blockIdx.z == 0) { A = A0; W = W0; bias = b0; Cv = C0; M = M0; }
    else                 { A = A1; W = W1; bias = b1; Cv = C1; M = M1; }
    if ((long)blockIdx.y * 128 >= (long)M) return;

    extern __shared__ char dsm[];
    const uint32_t base = smem_u32(dsm);
    const int tid = threadIdx.x;
    const int warp = tid >> 5, lane = tid & 31;
    const int wm = warp >> 2, wn = warp & 3;
    const long bm = (long)blockIdx.y * 128;
    const long bn = (long)blockIdx.x * 128;
    const int gr = lane >> 2, tg = lane & 3;

    float acc[4][4][4];
    #pragma unroll
    for (int i = 0; i < 4; i++)
        #pragma unroll
        for (int j = 0; j < 4; j++) {
            acc[i][j][0] = 0.f; acc[i][j][1] = 0.f;
            acc[i][j][2] = 0.f; acc[i][j][3] = 0.f;
        }

    const int S = K >> 6;
    auto stage = [&](int s, int b) {
        const int k0 = s << 6;
        #pragma unroll
        for (int i = 0; i < 4; i++) {
            int ch = tid + (i << 8);          // 0..1023
            int r = ch >> 3, c = ch & 7;
            cp16(base + (uint32_t)(b*36864 + r*144 + c*16),
                 A + (bm + r)*(long)K + k0 + c*8);
            cp16(base + (uint32_t)(b*36864 + 18432 + r*144 + c*16),
                 W + (bn + r)*(long)K + k0 + c*8);
        }
    };

    stage(0, 0); CP_COMMIT();
    stage(1, 1); CP_COMMIT();

    for (int s = 0; s < S; s++) {
        if (s + 1 < S) { CP_WAIT(1); } else { CP_WAIT(0); }
        __syncthreads();
        if (s + 2 < S) { stage(s + 2, (s + 2) % 3); CP_COMMIT(); }
        const uint32_t ab = base + (uint32_t)((s % 3) * 36864);
        const uint32_t bb = ab + 18432u;

        #pragma unroll
        for (int ks = 0; ks < 4; ks++) {
            uint32_t af[4][4], bf[4][2];
            #pragma unroll
            for (int mt = 0; mt < 4; mt++) {
                int row = wm*64 + mt*16 + (lane & 15);
                uint32_t p = ab + (uint32_t)(row*144 + (ks*2 + (lane >> 4))*16);
                asm volatile("ldmatrix.sync.aligned.m8n8.x4.shared.b16 {%0,%1,%2,%3}, [%4];"
                    : "=r"(af[mt][0]), "=r"(af[mt][1]), "=r"(af[mt][2]), "=r"(af[mt][3])
                    : "r"(p));
            }
            #pragma unroll
            for (int np = 0; np < 2; np++) {
                int q = lane >> 3;
                int nrow = wn*32 + np*16 + (q >> 1)*8 + (lane & 7);
                uint32_t p = bb + (uint32_t)(nrow*144 + (ks*2 + (q & 1))*16);
                asm volatile("ldmatrix.sync.aligned.m8n8.x4.shared.b16 {%0,%1,%2,%3}, [%4];"
                    : "=r"(bf[2*np][0]), "=r"(bf[2*np][1]),
                      "=r"(bf[2*np+1][0]), "=r"(bf[2*np+1][1])
                    : "r"(p));
            }
            #pragma unroll
            for (int mt = 0; mt < 4; mt++)
                #pragma unroll
                for (int nt = 0; nt < 4; nt++) {
                    asm volatile(
                        "mma.sync.aligned.m16n8k16.row.col.f32.f16.f16.f32 "
                        "{%0,%1,%2,%3}, {%4,%5,%6,%7}, {%8,%9}, {%0,%1,%2,%3};"
                        : "+f"(acc[mt][nt][0]), "+f"(acc[mt][nt][1]),
                          "+f"(acc[mt][nt][2]), "+f"(acc[mt][nt][3])
                        : "r"(af[mt][0]), "r"(af[mt][1]), "r"(af[mt][2]), "r"(af[mt][3]),
                          "r"(bf[nt][0]), "r"(bf[nt][1]));
                }
        }
    }

    // epilogue
    #pragma unroll
    for (int mt = 0; mt < 4; mt++) {
        long row0 = bm + wm*64 + mt*16 + gr;
        #pragma unroll
        for (int nt = 0; nt < 4; nt++) {
            int col0 = (int)bn + wn*32 + nt*8 + tg*2;
            float bv0 = __ldg(bias + col0);
            float bv1 = __ldg(bias + col0 + 1);
            float v00 = acc[mt][nt][0] + bv0;
            float v01 = acc[mt][nt][1] + bv1;
            float v10 = acc[mt][nt][2] + bv0;
            float v11 = acc[mt][nt][3] + bv1;
            if (EPI == 1) {
                v00 = fmaxf(v00, 0.f); v01 = fmaxf(v01, 0.f);
                v10 = fmaxf(v10, 0.f); v11 = fmaxf(v11, 0.f);
            }
            if (EPI == 2) {
                v00 = 1.f/(1.f+__expf(-v00)); v01 = 1.f/(1.f+__expf(-v01));
                v10 = 1.f/(1.f+__expf(-v10)); v11 = 1.f/(1.f+__expf(-v11));
            }
            if (OUT16) {
                __half* C = (__half*)Cv;
                *(__half2*)(C + row0*(long)N + col0)     = __floats2half2_rn(v00, v01);
                *(__half2*)(C + (row0+8)*(long)N + col0) = __floats2half2_rn(v10, v11);
            } else {
                float* C = (float*)Cv;
                *(float2*)(C + row0*(long)N + col0)     = make_float2(v00, v01);
                *(float2*)(C + (row0+8)*(long)N + col0) = make_float2(v10, v11);
            }
        }
    }
}

// ---------------- weight convert: all 8 weights, contiguous dst ----------------
__global__ void k_cvtall(long base4, long n4,
                         const float4* s0, const float4* s1, const float4* s2,
                         const float4* s3, const float4* s4, const float4* s5,
                         const float4* s6, const float4* s7, uint2* d) {
    long i = base4 + (long)blockIdx.x * blockDim.x + threadIdx.x;
    if (i >= base4 + n4) return;
    const float4* s; long off;
    if      (i <  786432) { s = s0; off = 0; }
    else if (i < 1048576) { s = s1; off =  786432; }
    else if (i < 2359296) { s = s2; off = 1048576; }
    else if (i < 3670016) { s = s3; off = 2359296; }
    else if (i < 4718592) { s = s4; off = 3670016; }
    else if (i < 5767168) { s = s5; off = 4718592; }
    else if (i < 6815744) { s = s6; off = 5767168; }
    else                  { s = s7; off = 6815744; }
    float4 v = s[i - off];
    __half2 a = __floats2half2_rn(v.x, v.y), b = __floats2half2_rn(v.z, v.w);
    d[i] = make_uint2(*(uint32_t*)&a, *(uint32_t*)&b);
}

// ---------------- small kernels ----------------
__global__ void k_src(const float* __restrict__ F, const float* __restrict__ R,
                      __half* __restrict__ srch) {
    long i8 = (long)blockIdx.x * blockDim.x + threadIdx.x;
    long r = i8 >> 7; int d8 = (int)(i8 & 127);
    int l = (int)(r % 6); long sbq = r / 6;
    const float4* F4 = (const float4*)F;
    float4 v0 = F4[i8*2], v1 = F4[i8*2+1];
    if (l > 0) {
        const float4* R4 = (const float4*)R;
        long rb = (sbq*5 + (l-1))*256 + d8*2;
        float4 e0 = R4[rb], e1 = R4[rb+1];
        v0.x+=e0.x; v0.y+=e0.y; v0.z+=e0.z; v0.w+=e0.w;
        v1.x+=e1.x; v1.y+=e1.y; v1.z+=e1.z; v1.w+=e1.w;
    }
    __half2 h0=__floats2half2_rn(v0.x,v0.y), h1=__floats2half2_rn(v0.z,v0.w);
    __half2 h2=__floats2half2_rn(v1.x,v1.y), h3=__floats2half2_rn(v1.z,v1.w);
    ((uint4*)srch)[i8] = make_uint4(*(uint32_t*)&h0,*(uint32_t*)&h1,*(uint32_t*)&h2,*(uint32_t*)&h3);
}
__global__ void k_gatherq(const __half* __restrict__ s, __half* __restrict__ q) {
    long idx = (long)blockIdx.x * blockDim.x + threadIdx.x;
    int i = (int)(idx >> 7), d8 = (int)(idx & 127);
    long rs;
    if (i < 10240) { int sp = i/2048, b = i%2048; rs = ((long)(sp+1)*2048 + b)*6; }
    else           { int j = i-10240; int m = j/2048, b = j%2048; rs = (long)b*6 + m + 1; }
    ((uint4*)q)[idx] = ((const uint4*)s)[rs*128 + d8];
}
__global__ void k_attn(const __half* __restrict__ q, const __half* __restrict__ kv,
                       __half* __restrict__ ctx) {
    int i = blockIdx.x, seq;
    if (i < 10240) { int sp = i/2048, b = i%2048; seq = (sp+1)*2048 + b; }
    else           { seq = (i - 10240) % 2048; }
    const int warp = threadIdx.x >> 5, lane = threadIdx.x & 31;
    const __half* kb = kv + (long)seq * 12288;
    for (int h = warp; h < 16; h += 8) {
        float2 qf = __half22float2(*(const __half2*)(q + (long)i*1024 + h*64 + lane*2));
        float sc[6];
        #pragma unroll
        for (int j = 0; j < 6; j++) {
            float2 kf = __half22float2(*(const __half2*)(kb + j*2048 + h*64 + lane*2));
            float p = qf.x*kf.x + qf.y*kf.y;
            #pragma unroll
            for (int o = 16; o; o >>= 1) p += __shfl_xor_sync(0xffffffffu, p, o);
            sc[j] = p * 0.125f;
        }
        float mx = sc[0];
        #pragma unroll
        for (int j = 1; j < 6; j++) mx = fmaxf(mx, sc[j]);
        float sum = 0.f;
        #pragma unroll
        for (int j = 0; j < 6; j++) { sc[j] = __expf(sc[j]-mx); sum += sc[j]; }
        float inv = 1.f/sum, o0 = 0.f, o1 = 0.f;
        #pragma unroll
        for (int j = 0; j < 6; j++) {
            float2 vf = __half22float2(*(const __half2*)(kb + j*2048 + 1024 + h*64 + lane*2));
            o0 = fmaf(sc[j]*inv, vf.x, o0); o1 = fmaf(sc[j]*inv, vf.y, o1);
        }
        *(__half2*)(ctx + (long)i*1024 + h*64 + lane*2) = __floats2half2_rn(o0, o1);
    }
}
__global__ void k_scatter(const __half* __restrict__ msg,
                          __half* __restrict__ a1, __half* __restrict__ a2) {
    long idx = (long)blockIdx.x * blockDim.x + threadIdx.x;
    int i = (int)(idx >> 7), d8 = (int)(idx & 127);
    uint4 v = ((const uint4*)msg)[idx];
    if (i < 10240) { int sp = i/2048, b = i%2048; ((uint4*)a1)[(long)b*640 + sp*128 + d8] = v; }
    else { int j = i-10240; int m = j/2048, b = j%2048; ((uint4*)a2)[(long)b*640 + m*128 + d8] = v; }
}
__device__ __forceinline__ float bsum(float v) {
    __shared__ float sh[9];
    int lane = threadIdx.x & 31, w = threadIdx.x >> 5;
    #pragma unroll
    for (int o = 16; o; o >>= 1) v += __shfl_xor_sync(0xffffffffu, v, o);
    if (lane == 0) sh[w] = v;
    __syncthreads();
    if (w == 0) {
        float r = (lane < 8) ? sh[lane] : 0.f;
        #pragma unroll
        for (int o = 4; o; o >>= 1) r += __shfl_xor_sync(0xffffffffu, r, o);
        if (lane == 0) sh[8] = r;
    }
    __syncthreads();
    float out = sh[8];
    __syncthreads();
    return out;
}
__device__ __forceinline__ void ln_row(const float* pa, const float* pb,
                                       const float* g, const float* bv,
                                       float* po, __half* ph) {
    int tid = threadIdx.x;
    float v[4];
    #pragma unroll
    for (int t = 0; t < 4; t++) v[t] = pa[tid + t*256] + pb[tid + t*256];
    float mu = bsum(v[0]+v[1]+v[2]+v[3]) * (1.f/1024.f);
    float qv = 0.f;
    #pragma unroll
    for (int t = 0; t < 4; t++) { float d = v[t]-mu; qv += d*d; }
    float r = rsqrtf(bsum(qv) * (1.f/1024.f) + 1e-5f);
    #pragma unroll
    for (int t = 0; t < 4; t++) {
        int idx = tid + t*256;
        float o = (v[t]-mu)*r*g[idx] + bv[idx];
        po[idx] = o;
        if (ph) ph[idx] = __float2half_rn(o);
    }
}
// merged LN1 (rows 0..10239) + LN3 (rows 10240..12287)
__global__ void k_ln13(const float* F, const float* aggv, const float* nagg,
                       const float* g1, const float* b1v,
                       const float* g3, const float* b3v,
                       float* h1, __half* h1h, float* s1, __half* s1h) {
    int row = blockIdx.x;
    if (row < 10240) {
        int b = row/5, m = row%5;
        ln_row(F + ((long)b*6+1+m)*1024, aggv + (long)b*1024, g1, b1v,
               h1 + (long)row*1024, h1h + (long)row*1024);
    } else {
        int b = row - 10240;
        ln_row(F + (long)b*6144, nagg + (long)b*1024, g3, b3v,
               s1 + (long)b*1024, s1h + (long)b*1024);
    }
}
// merged LN2 + LN4 -> write final output slices
__global__ void k_ln24(const float* h1, const float* f1, const float* s1, const float* f2,
                       const float* g2, const float* b2v,
                       const float* g4, const float* b4v, float* out) {
    int row = blockIdx.x;
    if (row < 10240) {
        int b = row/5, m = row%5;
        ln_row(h1 + (long)row*1024, f1 + (long)row*1024, g2, b2v,
               out + ((long)b*6+1+m)*1024, (__half*)0);
    } else {
        int b = row - 10240;
        ln_row(s1 + (long)b*1024, f2 + (long)b*1024, g4, b4v,
               out + (long)b*6144, (__half*)0);
    }
}

// ---------------- host ----------------
template<typename T> static T* sym(const void* s) {
    void* p = nullptr; cudaGetSymbolAddress(&p, s); return (T*)p;
}

extern "C" void kernel_launch(void* const* d_in, const int* in_sizes, int n_in,
                              void* d_out, int out_size) {
    (void)in_sizes; (void)n_in; (void)out_size;
    const float *F=(const float*)d_in[0], *R=(const float*)d_in[1];
    const float *w_in=(const float*)d_in[2], *b_in=(const float*)d_in[3];
    const float *w_out=(const float*)d_in[4], *b_out=(const float*)d_in[5];
    const float *ln1g=(const float*)d_in[6], *ln1b=(const float*)d_in[7];
    const float *ln2g=(const float*)d_in[8], *ln2b=(const float*)d_in[9];
    const float *ln3g=(const float*)d_in[10], *ln3b=(const float*)d_in[11];
    const float *ln4g=(const float*)d_in[12], *ln4b=(const float*)d_in[13];
    const float *f1w1=(const float*)d_in[14], *f1b1=(const float*)d_in[15];
    const float *f1w2=(const float*)d_in[16], *f1b2=(const float*)d_in[17];
    const float *f2w1=(const float*)d_in[18], *f2b1=(const float*)d_in[19];
    const float *f2w2=(const float*)d_in[20], *f2b2=(const float*)d_in[21];
    const float *a1w=(const float*)d_in[22], *a1b=(const float*)d_in[23];
    const float *a2w=(const float*)d_in[24], *a2b=(const float*)d_in[25];
    float* out = (float*)d_out;

    __half *srch=sym<__half>(g_srch), *kvh=sym<__half>(g_kvh);
    __half *qsrch=sym<__half>(g_qsrch), *qh=sym<__half>(g_qh);
    __half *ctxh=sym<__half>(g_ctxh), *msgh=sym<__half>(g_msgh);
    __half *a1inh=sym<__half>(g_a1inh), *a2inh=sym<__half>(g_a2inh);
    float *aggv=sym<float>(g_aggv), *nagg=sym<float>(g_nagg);
    float *h1=sym<float>(g_h1), *f1=sym<float>(g_f1);
    float *s1=sym<float>(g_s1), *f2=sym<float>(g_f2);
    __half *h1h=sym<__half>(g_h1h), *r1h=sym<__half>(g_r1h);
    __half *s1h=sym<__half>(g_s1h), *r2h=sym<__half>(g_r2h);
    __half *wh=sym<__half>(g_wh);

    cudaFuncSetAttribute(hgemm<0,1>, cudaFuncAttributeMaxDynamicSharedMemorySize, SMB);
    cudaFuncSetAttribute(hgemm<0,0>, cudaFuncAttributeMaxDynamicSharedMemorySize, SMB);
    cudaFuncSetAttribute(hgemm<1,1>, cudaFuncAttributeMaxDynamicSharedMemorySize, SMB);
    cudaFuncSetAttribute(hgemm<2,0>, cudaFuncAttributeMaxDynamicSharedMemorySize, SMB);

    cudaMemcpyAsync(out, F, OUTN*sizeof(float), cudaMemcpyDeviceToDevice, 0);

    // 2 cvt launches (0,1), then src(2), gather(3), Q(4), KV(5) <- ncu -s 5 profiles KV
    k_cvtall<<<15360, 256>>>(0, 3932160,
        (const float4*)w_in, (const float4*)w_out, (const float4*)a1w, (const float4*)a2w,
        (const float4*)f1w1, (const float4*)f1w2, (const float4*)f2w1, (const float4*)f2w2,
        (uint2*)wh);
    k_cvtall<<<15360, 256>>>(3932160, 3932160,
        (const float4*)w_in, (const float4*)w_out, (const float4*)a1w, (const float4*)a2w,
        (const float4*)f1w1, (const float4*)f1w2, (const float4*)f2w1, (const float4*)f2w2,
        (uint2*)wh);

    k_src<<<NROW/2, 256>>>(F, R, srch);
    k_gatherq<<<NQ/2, 256>>>(srch, qsrch);

    hgemm<0,1><<<dim3(8, NQ/128, 1), 256, SMB>>>(1024, 1024,
        NQ, qsrch, wh+WIN, b_in, qh,  NQ, qsrch, wh+WIN, b_in, qh);
    hgemm<0,1><<<dim3(16, NROW/128, 1), 256, SMB>>>(2048, 1024,
        NROW, srch, wh+WIN+(size_t)1024*1024, b_in+1024, kvh,
        NROW, srch, wh+WIN+(size_t)1024*1024, b_in+1024, kvh);

    k_attn<<<NQ, 256>>>(qh, kvh, ctxh);

    hgemm<0,1><<<dim3(8, NQ/128, 1), 256, SMB>>>(1024, 1024,
        NQ, ctxh, wh+WOUT, b_out, msgh,  NQ, ctxh, wh+WOUT, b_out, msgh);
    k_scatter<<<NQ/2, 256>>>(msgh, a1inh, a2inh);

    // batched agg gates
    hgemm<2,0><<<dim3(8, Bb/128, 2), 256, SMB>>>(1024, 5120,
        Bb, a1inh, wh+A1W, a1b, aggv,  Bb, a2inh, wh+A2W, a2b, nagg);

    k_ln13<<<12288, 256>>>(F, aggv, nagg, ln1g, ln1b, ln3g, ln3b, h1, h1h, s1, s1h);

    // batched FFN in (relu) and out
    hgemm<1,1><<<dim3(32, (Bb*5)/128, 2), 256, SMB>>>(DFF, 1024,
        Bb*5, h1h, wh+F1W1, f1b1, r1h,  Bb, s1h, wh+F2W1, f2b1, r2h);
    hgemm<0,0><<<dim3(8, (Bb*5)/128, 2), 256, SMB>>>(1024, DFF,
        Bb*5, r1h, wh+F1W2, f1b2, f1,  Bb, r2h, wh+F2W2, f2b2, f2);

    k_ln24<<<12288, 256>>>(h1, f1, s1, f2, ln2g, ln2b, ln4g, ln4b, out);
}

// round 11
// speedup vs baseline: 1.4719x; 1.0316x over previous
#include <cuda_runtime.h>
#include <cuda_fp16.h>
#include <math.h>
#include <stdint.h>

#define Dm 1024
#define DFF 4096
#define Bb 2048
#define NROW 73728
#define NQ 20480
#define OUTN ((size_t)6*2048*6*1024)

// ---------------- scratch ----------------
__device__ __half g_srch [(size_t)NROW*Dm];
__device__ __half g_kvh  [(size_t)NROW*2048];
__device__ __half g_qh   [(size_t)NQ*Dm];
__device__ __half g_ctxh [(size_t)NQ*Dm];
__device__ __half g_a1inh[(size_t)Bb*5120];
__device__ __half g_a2inh[(size_t)Bb*5120];
__device__ float  g_aggv [(size_t)Bb*Dm];
__device__ float  g_nagg [(size_t)Bb*Dm];
__device__ float  g_h1   [(size_t)Bb*5*Dm];
__device__ __half g_h1h  [(size_t)Bb*5*Dm];
__device__ __half g_r1h  [(size_t)Bb*5*DFF];
__device__ float  g_f1   [(size_t)Bb*5*Dm];
__device__ float  g_s1   [(size_t)Bb*Dm];
__device__ __half g_s1h  [(size_t)Bb*Dm];
__device__ __half g_r2h  [(size_t)Bb*DFF];
__device__ float  g_f2   [(size_t)Bb*Dm];
__device__ __half g_wh   [(size_t)31457280];
#define WIN  0
#define WOUT 3145728
#define A1W  4194304
#define A2W  9437184
#define F1W1 14680064
#define F1W2 18874368
#define F2W1 23068672
#define F2W2 27262976

__device__ __forceinline__ uint32_t smem_u32(const void* p) {
    uint32_t a;
    asm("{ .reg .u64 t; cvta.to.shared.u64 t, %1; cvt.u32.u64 %0, t; }" : "=r"(a) : "l"(p));
    return a;
}
__device__ __forceinline__ void cp16(uint32_t dst, const __half* src) {
    asm volatile("cp.async.cg.shared.global [%0], [%1], 16;"
                 :: "r"(dst), "l"(__cvta_generic_to_global(src)) : "memory");
}
#define CP_COMMIT() asm volatile("cp.async.commit_group;" ::: "memory")
#define CP_WAIT(n)  asm volatile("cp.async.wait_group %0;" :: "n"(n) : "memory")

// scatter destination for out-projection row i, col c (half granularity)
__device__ __forceinline__ __half* scat_ptr(__half* a1, __half* a2, int i, int c) {
    if (i < 10240) return a1 + (long)(i & 2047)*5120 + (i >> 11)*1024 + c;
    int j = i - 10240;
    return a2 + (long)(j & 2047)*5120 + (j >> 11)*1024 + c;
}

// ---------------- f16 mma.sync GEMM, z-batched, opt gather-A / scatter-C ----------------
// CTA tile 128x128, BK=64, 256 thr (8 warps 2x4), warp tile 64x32.
// 3-stage cp.async, one barrier per K-step, rows padded to 144B.
#define SMB 110592
template<int EPI, int OUT16, int GATHER, int SCAT>
__global__ void __launch_bounds__(256, 2) hgemm(
    int N, int K,
    int M0, const __half* A0, const __half* W0, const float* b0, void* C0,
    int M1, const __half* A1, const __half* W1, const float* b1, void* C1,
    __half* sc1, __half* sc2)
{
    const __half* A; const __half* W; const float* bias; void* Cv; int M;
    if (blockIdx.z == 0) { A = A0; W = W0; bias = b0; Cv = C0; M = M0; }
    else                 { A = A1; W = W1; bias = b1; Cv = C1; M = M1; }
    if ((long)blockIdx.y * 128 >= (long)M) return;

    extern __shared__ char dsm[];
    const uint32_t base = smem_u32(dsm);
    const int tid = threadIdx.x;
    const int warp = tid >> 5, lane = tid & 31;
    const int wm = warp >> 2, wn = warp & 3;
    const long bm = (long)blockIdx.y * 128;
    const long bn = (long)blockIdx.x * 128;
    const int gr = lane >> 2, tg = lane & 3;

    float acc[4][4][4];
    #pragma unroll
    for (int i = 0; i < 4; i++)
        #pragma unroll
        for (int j = 0; j < 4; j++) {
            acc[i][j][0] = 0.f; acc[i][j][1] = 0.f;
            acc[i][j][2] = 0.f; acc[i][j][3] = 0.f;
        }

    const int S = K >> 6;
    auto stage = [&](int s, int b) {
        const int k0 = s << 6;
        #pragma unroll
        for (int i = 0; i < 4; i++) {
            int ch = tid + (i << 8);
            int r = ch >> 3, c = ch & 7;
            long rs;
            if (GATHER) {
                int gi = (int)bm + r;
                if (gi < 10240) { int sp = gi >> 11, b2 = gi & 2047; rs = ((long)(sp+1)*2048 + b2)*6; }
                else            { int j = gi - 10240; rs = (long)(j & 2047)*6 + (j >> 11) + 1; }
            } else rs = bm + r;
            cp16(base + (uint32_t)(b*36864 + r*144 + c*16),
                 A + rs*(long)K + k0 + c*8);
            cp16(base + (uint32_t)(b*36864 + 18432 + r*144 + c*16),
                 W + (bn + r)*(long)K + k0 + c*8);
        }
    };

    stage(0, 0); CP_COMMIT();
    stage(1, 1); CP_COMMIT();

    for (int s = 0; s < S; s++) {
        if (s + 1 < S) { CP_WAIT(1); } else { CP_WAIT(0); }
        __syncthreads();
        if (s + 2 < S) { stage(s + 2, (s + 2) % 3); CP_COMMIT(); }
        const uint32_t ab = base + (uint32_t)((s % 3) * 36864);
        const uint32_t bb = ab + 18432u;

        #pragma unroll
        for (int ks = 0; ks < 4; ks++) {
            uint32_t af[4][4], bf[4][2];
            #pragma unroll
            for (int mt = 0; mt < 4; mt++) {
                int row = wm*64 + mt*16 + (lane & 15);
                uint32_t p = ab + (uint32_t)(row*144 + (ks*2 + (lane >> 4))*16);
                asm volatile("ldmatrix.sync.aligned.m8n8.x4.shared.b16 {%0,%1,%2,%3}, [%4];"
                    : "=r"(af[mt][0]), "=r"(af[mt][1]), "=r"(af[mt][2]), "=r"(af[mt][3])
                    : "r"(p));
            }
            #pragma unroll
            for (int np = 0; np < 2; np++) {
                int q = lane >> 3;
                int nrow = wn*32 + np*16 + (q >> 1)*8 + (lane & 7);
                uint32_t p = bb + (uint32_t)(nrow*144 + (ks*2 + (q & 1))*16);
                asm volatile("ldmatrix.sync.aligned.m8n8.x4.shared.b16 {%0,%1,%2,%3}, [%4];"
                    : "=r"(bf[2*np][0]), "=r"(bf[2*np][1]),
                      "=r"(bf[2*np+1][0]), "=r"(bf[2*np+1][1])
                    : "r"(p));
            }
            #pragma unroll
            for (int mt = 0; mt < 4; mt++)
                #pragma unroll
                for (int nt = 0; nt < 4; nt++) {
                    asm volatile(
                        "mma.sync.aligned.m16n8k16.row.col.f32.f16.f16.f32 "
                        "{%0,%1,%2,%3}, {%4,%5,%6,%7}, {%8,%9}, {%0,%1,%2,%3};"
                        : "+f"(acc[mt][nt][0]), "+f"(acc[mt][nt][1]),
                          "+f"(acc[mt][nt][2]), "+f"(acc[mt][nt][3])
                        : "r"(af[mt][0]), "r"(af[mt][1]), "r"(af[mt][2]), "r"(af[mt][3]),
                          "r"(bf[nt][0]), "r"(bf[nt][1]));
                }
        }
    }

    // epilogue
    #pragma unroll
    for (int mt = 0; mt < 4; mt++) {
        long row0 = bm + wm*64 + mt*16 + gr;
        #pragma unroll
        for (int nt = 0; nt < 4; nt++) {
            int col0 = (int)bn + wn*32 + nt*8 + tg*2;
            float bv0 = __ldg(bias + col0);
            float bv1 = __ldg(bias + col0 + 1);
            float v00 = acc[mt][nt][0] + bv0;
            float v01 = acc[mt][nt][1] + bv1;
            float v10 = acc[mt][nt][2] + bv0;
            float v11 = acc[mt][nt][3] + bv1;
            if (EPI == 1) {
                v00 = fmaxf(v00, 0.f); v01 = fmaxf(v01, 0.f);
                v10 = fmaxf(v10, 0.f); v11 = fmaxf(v11, 0.f);
            }
            if (EPI == 2) {
                v00 = 1.f/(1.f+__expf(-v00)); v01 = 1.f/(1.f+__expf(-v01));
                v10 = 1.f/(1.f+__expf(-v10)); v11 = 1.f/(1.f+__expf(-v11));
            }
            if (SCAT) {
                *(__half2*)scat_ptr(sc1, sc2, (int)row0,     col0) = __floats2half2_rn(v00, v01);
                *(__half2*)scat_ptr(sc1, sc2, (int)row0 + 8, col0) = __floats2half2_rn(v10, v11);
            } else if (OUT16) {
                __half* C = (__half*)Cv;
                *(__half2*)(C + row0*(long)N + col0)     = __floats2half2_rn(v00, v01);
                *(__half2*)(C + (row0+8)*(long)N + col0) = __floats2half2_rn(v10, v11);
            } else {
                float* C = (float*)Cv;
                *(float2*)(C + row0*(long)N + col0)     = make_float2(v00, v01);
                *(float2*)(C + (row0+8)*(long)N + col0) = make_float2(v10, v11);
            }
        }
    }
}

// ---------------- weight convert ----------------
__global__ void k_cvtall(long base4, long n4,
                         const float4* s0, const float4* s1, const float4* s2,
                         const float4* s3, const float4* s4, const float4* s5,
                         const float4* s6, const float4* s7, uint2* d) {
    long i = base4 + (long)blockIdx.x * blockDim.x + threadIdx.x;
    if (i >= base4 + n4) return;
    const float4* s; long off;
    if      (i <  786432) { s = s0; off = 0; }
    else if (i < 1048576) { s = s1; off =  786432; }
    else if (i < 2359296) { s = s2; off = 1048576; }
    else if (i < 3670016) { s = s3; off = 2359296; }
    else if (i < 4718592) { s = s4; off = 3670016; }
    else if (i < 5767168) { s = s5; off = 4718592; }
    else if (i < 6815744) { s = s6; off = 5767168; }
    else                  { s = s7; off = 6815744; }
    float4 v = s[i - off];
    __half2 a = __floats2half2_rn(v.x, v.y), b = __floats2half2_rn(v.z, v.w);
    d[i] = make_uint2(*(uint32_t*)&a, *(uint32_t*)&b);
}

// ---------------- fused src-materialize + passthrough copy (slices 1..5) ----------------
__global__ void k_srcout(const float* __restrict__ F, const float* __restrict__ R,
                         __half* __restrict__ srch, float* __restrict__ out) {
    long i8 = (long)blockIdx.x * blockDim.x + threadIdx.x;   // 8-elem chunk
    long r = i8 >> 7; int d8 = (int)(i8 & 127);
    int l = (int)(r % 6); long sbq = r / 6;
    const float4* F4 = (const float4*)F;
    float4 v0 = F4[i8*2], v1 = F4[i8*2+1];
    if (r >= 12288) {                 // s>0: passthrough copy of raw features
        ((float4*)out)[i8*2]   = v0;
        ((float4*)out)[i8*2+1] = v1;
    }
    if (l > 0) {
        const float4* R4 = (const float4*)R;
        long rb = (sbq*5 + (l-1))*256 + d8*2;
        float4 e0 = R4[rb], e1 = R4[rb+1];
        v0.x+=e0.x; v0.y+=e0.y; v0.z+=e0.z; v0.w+=e0.w;
        v1.x+=e1.x; v1.y+=e1.y; v1.z+=e1.z; v1.w+=e1.w;
    }
    __half2 h0=__floats2half2_rn(v0.x,v0.y), h1=__floats2half2_rn(v0.z,v0.w);
    __half2 h2=__floats2half2_rn(v1.x,v1.y), h3=__floats2half2_rn(v1.z,v1.w);
    ((uint4*)srch)[i8] = make_uint4(*(uint32_t*)&h0,*(uint32_t*)&h1,*(uint32_t*)&h2,*(uint32_t*)&h3);
}

// ---------------- attention ----------------
__global__ void k_attn(const __half* __restrict__ q, const __half* __restrict__ kv,
                       __half* __restrict__ ctx) {
    int i = blockIdx.x, seq;
    if (i < 10240) { int sp = i/2048, b = i%2048; seq = (sp+1)*2048 + b; }
    else           { seq = (i - 10240) % 2048; }
    const int warp = threadIdx.x >> 5, lane = threadIdx.x & 31;
    const __half* kb = kv + (long)seq * 12288;
    for (int h = warp; h < 16; h += 8) {
        float2 qf = __half22float2(*(const __half2*)(q + (long)i*1024 + h*64 + lane*2));
        float sc[6];
        #pragma unroll
        for (int j = 0; j < 6; j++) {
            float2 kf = __half22float2(*(const __half2*)(kb + j*2048 + h*64 + lane*2));
            float p = qf.x*kf.x + qf.y*kf.y;
            #pragma unroll
            for (int o = 16; o; o >>= 1) p += __shfl_xor_sync(0xffffffffu, p, o);
            sc[j] = p * 0.125f;
        }
        float mx = sc[0];
        #pragma unroll
        for (int j = 1; j < 6; j++) mx = fmaxf(mx, sc[j]);
        float sum = 0.f;
        #pragma unroll
        for (int j = 0; j < 6; j++) { sc[j] = __expf(sc[j]-mx); sum += sc[j]; }
        float inv = 1.f/sum, o0 = 0.f, o1 = 0.f;
        #pragma unroll
        for (int j = 0; j < 6; j++) {
            float2 vf = __half22float2(*(const __half2*)(kb + j*2048 + 1024 + h*64 + lane*2));
            o0 = fmaf(sc[j]*inv, vf.x, o0); o1 = fmaf(sc[j]*inv, vf.y, o1);
        }
        *(__half2*)(ctx + (long)i*1024 + h*64 + lane*2) = __floats2half2_rn(o0, o1);
    }
}

// ---------------- LayerNorm ----------------
__device__ __forceinline__ float bsum(float v) {
    __shared__ float sh[9];
    int lane = threadIdx.x & 31, w = threadIdx.x >> 5;
    #pragma unroll
    for (int o = 16; o; o >>= 1) v += __shfl_xor_sync(0xffffffffu, v, o);
    if (lane == 0) sh[w] = v;
    __syncthreads();
    if (w == 0) {
        float r = (lane < 8) ? sh[lane] : 0.f;
        #pragma unroll
        for (int o = 4; o; o >>= 1) r += __shfl_xor_sync(0xffffffffu, r, o);
        if (lane == 0) sh[8] = r;
    }
    __syncthreads();
    float out = sh[8];
    __syncthreads();
    return out;
}
__device__ __forceinline__ void ln_row(const float* pa, const float* pb,
                                       const float* g, const float* bv,
                                       float* po, __half* ph) {
    int tid = threadIdx.x;
    float v[4];
    #pragma unroll
    for (int t = 0; t < 4; t++) v[t] = pa[tid + t*256] + pb[tid + t*256];
    float mu = bsum(v[0]+v[1]+v[2]+v[3]) * (1.f/1024.f);
    float qv = 0.f;
    #pragma unroll
    for (int t = 0; t < 4; t++) { float d = v[t]-mu; qv += d*d; }
    float r = rsqrtf(bsum(qv) * (1.f/1024.f) + 1e-5f);
    #pragma unroll
    for (int t = 0; t < 4; t++) {
        int idx = tid + t*256;
        float o = (v[t]-mu)*r*g[idx] + bv[idx];
        po[idx] = o;
        if (ph) ph[idx] = __float2half_rn(o);
    }
}
__global__ void k_ln13(const float* F, const float* aggv, const float* nagg,
                       const float* g1, const float* b1v,
                       const float* g3, const float* b3v,
                       float* h1, __half* h1h, float* s1, __half* s1h) {
    int row = blockIdx.x;
    if (row < 10240) {
        int b = row/5, m = row%5;
        ln_row(F + ((long)b*6+1+m)*1024, aggv + (long)b*1024, g1, b1v,
               h1 + (long)row*1024, h1h + (long)row*1024);
    } else {
        int b = row - 10240;
        ln_row(F + (long)b*6144, nagg + (long)b*1024, g3, b3v,
               s1 + (long)b*1024, s1h + (long)b*1024);
    }
}
__global__ void k_ln24(const float* h1, const float* f1, const float* s1, const float* f2,
                       const float* g2, const float* b2v,
                       const float* g4, const float* b4v, float* out) {
    int row = blockIdx.x;
    if (row < 10240) {
        int b = row/5, m = row%5;
        ln_row(h1 + (long)row*1024, f1 + (long)row*1024, g2, b2v,
               out + ((long)b*6+1+m)*1024, (__half*)0);
    } else {
        int b = row - 10240;
        ln_row(s1 + (long)b*1024, f2 + (long)b*1024, g4, b4v,
               out + (long)b*6144, (__half*)0);
    }
}

// ---------------- host ----------------
template<typename T> static T* sym(const void* s) {
    void* p = nullptr; cudaGetSymbolAddress(&p, s); return (T*)p;
}

extern "C" void kernel_launch(void* const* d_in, const int* in_sizes, int n_in,
                              void* d_out, int out_size) {
    (void)in_sizes; (void)n_in; (void)out_size;
    const float *F=(const float*)d_in[0], *R=(const float*)d_in[1];
    const float *w_in=(const float*)d_in[2], *b_in=(const float*)d_in[3];
    const float *w_out=(const float*)d_in[4], *b_out=(const float*)d_in[5];
    const float *ln1g=(const float*)d_in[6], *ln1b=(const float*)d_in[7];
    const float *ln2g=(const float*)d_in[8], *ln2b=(const float*)d_in[9];
    const float *ln3g=(const float*)d_in[10], *ln3b=(const float*)d_in[11];
    const float *ln4g=(const float*)d_in[12], *ln4b=(const float*)d_in[13];
    const float *f1w1=(const float*)d_in[14], *f1b1=(const float*)d_in[15];
    const float *f1w2=(const float*)d_in[16], *f1b2=(const float*)d_in[17];
    const float *f2w1=(const float*)d_in[18], *f2b1=(const float*)d_in[19];
    const float *f2w2=(const float*)d_in[20], *f2b2=(const float*)d_in[21];
    const float *a1w=(const float*)d_in[22], *a1b=(const float*)d_in[23];
    const float *a2w=(const float*)d_in[24], *a2b=(const float*)d_in[25];
    float* out = (float*)d_out;

    __half *srch=sym<__half>(g_srch), *kvh=sym<__half>(g_kvh);
    __half *qh=sym<__half>(g_qh), *ctxh=sym<__half>(g_ctxh);
    __half *a1inh=sym<__half>(g_a1inh), *a2inh=sym<__half>(g_a2inh);
    float *aggv=sym<float>(g_aggv), *nagg=sym<float>(g_nagg);
    float *h1=sym<float>(g_h1), *f1=sym<float>(g_f1);
    float *s1=sym<float>(g_s1), *f2=sym<float>(g_f2);
    __half *h1h=sym<__half>(g_h1h), *r1h=sym<__half>(g_r1h);
    __half *s1h=sym<__half>(g_s1h), *r2h=sym<__half>(g_r2h);
    __half *wh=sym<__half>(g_wh);

    cudaFuncSetAttribute(hgemm<0,1,0,0>, cudaFuncAttributeMaxDynamicSharedMemorySize, SMB);
    cudaFuncSetAttribute(hgemm<0,1,1,0>, cudaFuncAttributeMaxDynamicSharedMemorySize, SMB);
    cudaFuncSetAttribute(hgemm<0,1,0,1>, cudaFuncAttributeMaxDynamicSharedMemorySize, SMB);
    cudaFuncSetAttribute(hgemm<0,0,0,0>, cudaFuncAttributeMaxDynamicSharedMemorySize, SMB);
    cudaFuncSetAttribute(hgemm<1,1,0,0>, cudaFuncAttributeMaxDynamicSharedMemorySize, SMB);
    cudaFuncSetAttribute(hgemm<2,0,0,0>, cudaFuncAttributeMaxDynamicSharedMemorySize, SMB);

    k_cvtall<<<15360, 256>>>(0, 3932160,
        (const float4*)w_in, (const float4*)w_out, (const float4*)a1w, (const float4*)a2w,
        (const float4*)f1w1, (const float4*)f1w2, (const float4*)f2w1, (const float4*)f2w2,
        (uint2*)wh);
    k_cvtall<<<15360, 256>>>(3932160, 3932160,
        (const float4*)w_in, (const float4*)w_out, (const float4*)a1w, (const float4*)a2w,
        (const float4*)f1w1, (const float4*)f1w2, (const float4*)f2w1, (const float4*)f2w2,
        (uint2*)wh);

    // fused src materialization + passthrough copy (slices 1..5; slice 0 via ln24)
    k_srcout<<<NROW/2, 256>>>(F, R, srch, out);

    // KV for all rows
    hgemm<0,1,0,0><<<dim3(16, NROW/128, 1), 256, SMB>>>(2048, 1024,
        NROW, srch, wh+WIN+(size_t)1024*1024, b_in+1024, kvh,
        NROW, srch, wh+WIN+(size_t)1024*1024, b_in+1024, kvh, (void*)0 ? (__half*)0 : (__half*)0, (__half*)0);
    // Q with fused gather
    hgemm<0,1,1,0><<<dim3(8, NQ/128, 1), 256, SMB>>>(1024, 1024,
        NQ, srch, wh+WIN, b_in, qh,  NQ, srch, wh+WIN, b_in, qh, (__half*)0, (__half*)0);

    k_attn<<<NQ, 256>>>(qh, kvh, ctxh);

    // out projection with fused scatter
    hgemm<0,1,0,1><<<dim3(8, NQ/128, 1), 256, SMB>>>(1024, 1024,
        NQ, ctxh, wh+WOUT, b_out, (void*)0,  NQ, ctxh, wh+WOUT, b_out, (void*)0,
        a1inh, a2inh);

    // batched agg gates
    hgemm<2,0,0,0><<<dim3(8, Bb/128, 2), 256, SMB>>>(1024, 5120,
        Bb, a1inh, wh+A1W, a1b, aggv,  Bb, a2inh, wh+A2W, a2b, nagg, (__half*)0, (__half*)0);

    k_ln13<<<12288, 256>>>(F, aggv, nagg, ln1g, ln1b, ln3g, ln3b, h1, h1h, s1, s1h);

    hgemm<1,1,0,0><<<dim3(32, (Bb*5)/128, 2), 256, SMB>>>(DFF, 1024,
        Bb*5, h1h, wh+F1W1, f1b1, r1h,  Bb, s1h, wh+F2W1, f2b1, r2h, (__half*)0, (__half*)0);
    hgemm<0,0,0,0><<<dim3(8, (Bb*5)/128, 2), 256, SMB>>>(1024, DFF,
        Bb*5, r1h, wh+F1W2, f1b2, f1,  Bb, r2h, wh+F2W2, f2b2, f2, (__half*)0, (__half*)0);

    k_ln24<<<12288, 256>>>(h1, f1, s1, f2, ln2g, ln2b, ln4g, ln4b, out);
}